// round 10
// baseline (speedup 1.0000x reference)
#include <cuda_runtime.h>
#include <stdint.h>

// TopKTokenChoiceRouter: x(8192,4096) fp32 @ W^T(4096,64) -> softmax -> top2.
// 3xTF32 mma.sync.m16n8k8 (compute_100-safe).
// R10 = R6 warp structure + (a) fragment-order W -> 1 conflict-free LDS.128 per
// B fragment, (b) NSPLIT=4 + NSTAGE=3 -> 2 CTAs/SM (16 warps/SM) occupancy.
// Out layout (validated): [weights M*2 f32][indices-as-f32 M*2].

#define K_DIM   4096
#define NE      64
#define BM      128
#define BK      32
#define NSPLIT  4
#define KSPLIT  (K_DIM / NSPLIT)      // 1024
#define NCH     (KSPLIT / BK)         // 32 chunks per split
#define NCHTOT  (K_DIM / BK)          // 128 chunks total
#define NSTAGE  3
#define MMAX    8192

#define ROWSTR  36                    // A row stride (floats), conflict-free frags
#define A_BYTES (BM * ROWSTR * 4)     // 18432
#define B_BYTES 16384                 // 1024 x 16B frag records per chunk
#define OFF_B   A_BYTES
#define STAGE_BYTES (A_BYTES + B_BYTES)              // 34816
#define SMEM_TOTAL (NSTAGE * STAGE_BYTES)            // 104448 -> 2 CTAs/SM

typedef unsigned int u32;

__device__ float g_partials[(size_t)NSPLIT * MMAX * NE];   // 8 MB
__device__ uint4 g_Wfrag[(size_t)NCHTOT * 1024];           // 2 MB, fragment order

__device__ __forceinline__ u32 smem_u32(const void* p){
    u32 a; asm("{ .reg .u64 t; cvta.to.shared.u64 t, %1; cvt.u32.u64 %0, t; }" : "=r"(a) : "l"(p));
    return a;
}
__device__ __forceinline__ void split_tf32(float v, u32& hi, u32& lo){
    asm("cvt.rna.tf32.f32 %0, %1;" : "=r"(hi) : "f"(v));
    float r = v - __uint_as_float(hi);
    asm("cvt.rna.tf32.f32 %0, %1;" : "=r"(lo) : "f"(r));
}
__device__ __forceinline__ void cpa16(u32 dst, const void* src){
    asm volatile("cp.async.ca.shared.global [%0], [%1], 16;" :: "r"(dst), "l"(src));
}
__device__ __forceinline__ void cpa_commit(){
    asm volatile("cp.async.commit_group;" ::: "memory");
}
template<int N> __device__ __forceinline__ void cpa_wait(){
    asm volatile("cp.async.wait_group %0;" :: "n"(N) : "memory");
}
__device__ __forceinline__ float lds32(u32 a){
    float v; asm volatile("ld.shared.f32 %0, [%1];" : "=f"(v) : "r"(a));
    return v;
}
__device__ __forceinline__ uint4 lds128(u32 a){
    uint4 v;
    asm volatile("ld.shared.v4.b32 {%0,%1,%2,%3}, [%4];"
                 : "=r"(v.x), "=r"(v.y), "=r"(v.z), "=r"(v.w) : "r"(a));
    return v;
}
__device__ __forceinline__ void mma8(float (&d)[4], const u32 (&a)[4], u32 b0, u32 b1){
    asm volatile("mma.sync.aligned.m16n8k8.row.col.f32.tf32.tf32.f32 "
        "{%0,%1,%2,%3}, {%4,%5,%6,%7}, {%8,%9}, {%0,%1,%2,%3};"
        : "+f"(d[0]), "+f"(d[1]), "+f"(d[2]), "+f"(d[3])
        : "r"(a[0]), "r"(a[1]), "r"(a[2]), "r"(a[3]), "r"(b0), "r"(b1));
}

// ---------------- W pre-split into fragment order ----------------
// Record index within chunk ch: rec = (ks*4 + lk)*64 + n  (byte off = rec*16).
// Record = {hi(k0), hi(k0+4), lo(k0), lo(k0+4)}, k0 = ch*32 + ks*8 + lk.
__global__ __launch_bounds__(256) void conv_w_kernel(const float* __restrict__ W){
    const int gid = blockIdx.x * 256 + threadIdx.x;     // 0 .. 131071
    const int ch  = gid >> 10;
    const int rem = gid & 1023;
    const int n   = rem >> 4;
    const int ks  = (rem >> 2) & 3;
    const int lk  = rem & 3;
    const int k0  = ch * BK + ks * 8 + lk;
    const float* wr = W + (size_t)n * K_DIM;
    uint4 o;
    u32 l0, l1;
    split_tf32(wr[k0],     o.x, l0);
    split_tf32(wr[k0 + 4], o.y, l1);
    o.z = l0; o.w = l1;
    g_Wfrag[(size_t)ch * 1024 + (ks * 4 + lk) * 64 + n] = o;
}

// ---------------- GEMM (split-K 4, 3xTF32) ----------------
__global__ __launch_bounds__(256, 2) void gemm_kernel(
    const float* __restrict__ x, int M)
{
    extern __shared__ char smem[];
    const u32 sbase = smem_u32(smem);
    const int tid  = threadIdx.x;
    const int wid  = tid >> 5;
    const int lane = tid & 31;
    const int m_base = blockIdx.x * BM;
    const int split  = blockIdx.y;
    const int k0     = split * KSPLIT;

    // cp.async: A 1024 float4/stage (4/thread), B 1024 uint4/stage (4/thread)
    const float* srcA[4]; u32 dstA[4];
    #pragma unroll
    for (int i = 0; i < 4; i++) {
        const int idx = tid + 256 * i;
        const int row = idx >> 3, f4 = idx & 7;
        srcA[i] = x + (size_t)(m_base + row) * K_DIM + k0 + f4 * 4;
        dstA[i] = row * (ROWSTR * 4) + f4 * 16;
    }
    const uint4* srcB = g_Wfrag + (size_t)split * NCH * 1024 + tid;

    #define ISSUE_STAGE(ch) do {                                              \
        const u32 st = sbase + (u32)((ch) % NSTAGE) * STAGE_BYTES;            \
        _Pragma("unroll")                                                     \
        for (int i = 0; i < 4; i++) {                                         \
            cpa16(st + dstA[i], srcA[i] + (ch) * BK);                         \
            cpa16(st + OFF_B + (u32)(tid + 256 * i) * 16,                     \
                  srcB + (size_t)(ch) * 1024 + 256 * i);                      \
        }                                                                     \
    } while (0)

    ISSUE_STAGE(0); cpa_commit();
    ISSUE_STAGE(1); cpa_commit();
    ISSUE_STAGE(2); cpa_commit();

    float c[8][4];
    #pragma unroll
    for (int nf = 0; nf < 8; nf++)
        #pragma unroll
        for (int q = 0; q < 4; q++) c[nf][q] = 0.f;

    const int m0 = wid * 16;
    const u32 aRowOff = (u32)(m0 + (lane >> 2)) * (ROWSTR * 4);
    const u32 aColOff = (u32)(lane & 3) * 4;
    // B record for (ks, nf): rec = (ks*4 + lane&3)*64 + nf*8 + (lane>>2)
    const u32 bLane = (u32)(((lane & 3) * 64 + (lane >> 2)) * 16);

    #pragma unroll 1
    for (int ch = 0; ch < NCH; ch++) {
        cpa_wait<2>();
        __syncthreads();

        const u32 st = sbase + (u32)(ch % NSTAGE) * STAGE_BYTES;
        const u32 stB = st + OFF_B + bLane;
        #pragma unroll
        for (int ks = 0; ks < 4; ks++) {
            const u32 aA = st + aRowOff + (u32)ks * 32 + aColOff;
            float a0 = lds32(aA);
            float a1 = lds32(aA + 8 * ROWSTR * 4);
            float a2 = lds32(aA + 16);
            float a3 = lds32(aA + 8 * ROWSTR * 4 + 16);
            u32 ahi[4], alo[4];
            split_tf32(a0, ahi[0], alo[0]);
            split_tf32(a1, ahi[1], alo[1]);
            split_tf32(a2, ahi[2], alo[2]);
            split_tf32(a3, ahi[3], alo[3]);

            #pragma unroll
            for (int nf = 0; nf < 8; nf++) {
                uint4 b = lds128(stB + (u32)(ks * 4 * 64 + nf * 8) * 16);
                mma8(c[nf], ahi, b.x, b.y);   // hi*hi
                mma8(c[nf], ahi, b.z, b.w);   // hi*lo
                mma8(c[nf], alo, b.x, b.y);   // lo*hi
            }
        }

        __syncthreads();
        if (ch + 3 < NCH) ISSUE_STAGE(ch + 3);
        cpa_commit();
    }

    // write partial logits [split][token][expert]
    const int t0  = m_base + m0 + (lane >> 2);
    const int col = (lane & 3) * 2;
    #pragma unroll
    for (int nf = 0; nf < 8; nf++) {
        float* p0 = g_partials + ((size_t)split * M + t0) * NE + nf * 8 + col;
        *(float2*)p0            = make_float2(c[nf][0], c[nf][1]);
        *(float2*)(p0 + 8 * NE) = make_float2(c[nf][2], c[nf][3]);
    }
    #undef ISSUE_STAGE
}

// ---------------- reduce + softmax + top2 ----------------
__global__ __launch_bounds__(256) void reduce_topk_kernel(
    float* __restrict__ out, int M, int write_idx)
{
    const int warp = threadIdx.x >> 5;
    const int lane = threadIdx.x & 31;
    const int t = blockIdx.x * 8 + warp;
    if (t >= M) return;

    float2 s = make_float2(0.f, 0.f);
    const float* p = g_partials + (size_t)t * NE + 2 * lane;
    #pragma unroll
    for (int si = 0; si < NSPLIT; si++) {
        float2 v = *(const float2*)(p + (size_t)si * M * NE);
        s.x += v.x; s.y += v.y;
    }

    float a1, a2; int i1, i2;
    if (s.x >= s.y) { a1 = s.x; i1 = 2 * lane;     a2 = s.y; i2 = 2 * lane + 1; }
    else            { a1 = s.y; i1 = 2 * lane + 1; a2 = s.x; i2 = 2 * lane;     }

    #pragma unroll
    for (int off = 16; off > 0; off >>= 1) {
        float b1 = __shfl_xor_sync(0xffffffffu, a1, off);
        float b2 = __shfl_xor_sync(0xffffffffu, a2, off);
        int  bi1 = __shfl_xor_sync(0xffffffffu, i1, off);
        int  bi2 = __shfl_xor_sync(0xffffffffu, i2, off);
        if (b1 > a1 || (b1 == a1 && bi1 < i1)) {
            if (b2 > a1 || (b2 == a1 && bi2 < i1)) { a1 = b1; i1 = bi1; a2 = b2; i2 = bi2; }
            else                                   { a2 = a1; i2 = i1;  a1 = b1; i1 = bi1; }
        } else {
            if (b1 > a2 || (b1 == a2 && bi1 < i2)) { a2 = b1; i2 = bi1; }
        }
    }

    float ex = __expf(s.x - a1) + __expf(s.y - a1);
    #pragma unroll
    for (int off = 16; off > 0; off >>= 1)
        ex += __shfl_xor_sync(0xffffffffu, ex, off);

    if (lane == 0) {
        const float inv = 1.0f / ex;
        out[2 * t + 0] = inv;
        out[2 * t + 1] = __expf(a2 - a1) * inv;
        if (write_idx) {
            out[2 * M + 2 * t + 0] = (float)i1;
            out[2 * M + 2 * t + 1] = (float)i2;
        }
    }
}

extern "C" void kernel_launch(void* const* d_in, const int* in_sizes, int n_in,
                              void* d_out, int out_size) {
    const float* x = (const float*)d_in[0];   // 8192 x 4096 fp32
    const float* W = (const float*)d_in[1];   // 64 x 4096 fp32
    float* out = (float*)d_out;

    const int M = in_sizes[0] / K_DIM;        // 8192
    const int write_idx = (out_size >= 4 * M) ? 1 : 0;

    cudaFuncSetAttribute(gemm_kernel,
                         cudaFuncAttributeMaxDynamicSharedMemorySize, SMEM_TOTAL);

    conv_w_kernel<<<512, 256>>>(W);
    dim3 grid(M / BM, NSPLIT);
    gemm_kernel<<<grid, 256, SMEM_TOTAL>>>(x, M);
    reduce_topk_kernel<<<(M + 7) / 8, 256>>>(out, M, write_idx);
}

// round 11
// speedup vs baseline: 2.1326x; 2.1326x over previous
#include <cuda_runtime.h>
#include <stdint.h>

// TopKTokenChoiceRouter: x(8192,4096) fp32 @ W^T(4096,64) -> softmax -> top2.
// 3xTF32 mma.sync.m16n8k8 (compute_100-safe).
// R11 = exact R6 (88.2us) base; single delta: warp tile m16n64 -> m32n32
// (4 m-bands x 2 n-halves) halving per-warp B smem reads.
// Out layout (validated): [weights M*2 f32][indices-as-f32 M*2].

#define K_DIM   4096
#define NE      64
#define BM      128
#define BK      32
#define NSPLIT  2
#define KSPLIT  (K_DIM / NSPLIT)      // 2048
#define NCH     (KSPLIT / BK)         // 64 chunks
#define NSTAGE  4
#define MMAX    8192

#define ROWSTR  36                    // padded row stride (floats): conflict-free frags
#define A_BYTES (BM * ROWSTR * 4)     // 18432
#define B_BYTES (NE * ROWSTR * 4)     // 9216
#define STAGE_BYTES (A_BYTES + 2 * B_BYTES)          // 36864
#define OFF_BH  A_BYTES
#define OFF_BL  (A_BYTES + B_BYTES)
#define SMEM_TOTAL (NSTAGE * STAGE_BYTES)            // 147456

typedef unsigned int u32;

__device__ float g_partials[(size_t)NSPLIT * MMAX * NE];  // 4 MB
__device__ u32   g_Whi[NE * K_DIM];                       // 1 MB
__device__ u32   g_Wlo[NE * K_DIM];                       // 1 MB

__device__ __forceinline__ u32 smem_u32(const void* p){
    u32 a; asm("{ .reg .u64 t; cvta.to.shared.u64 t, %1; cvt.u32.u64 %0, t; }" : "=r"(a) : "l"(p));
    return a;
}
__device__ __forceinline__ void split_tf32(float v, u32& hi, u32& lo){
    asm("cvt.rna.tf32.f32 %0, %1;" : "=r"(hi) : "f"(v));
    float r = v - __uint_as_float(hi);
    asm("cvt.rna.tf32.f32 %0, %1;" : "=r"(lo) : "f"(r));
}
__device__ __forceinline__ void cpa16(u32 dst, const void* src){
    asm volatile("cp.async.ca.shared.global [%0], [%1], 16;" :: "r"(dst), "l"(src));
}
__device__ __forceinline__ void cpa_commit(){
    asm volatile("cp.async.commit_group;" ::: "memory");
}
template<int N> __device__ __forceinline__ void cpa_wait(){
    asm volatile("cp.async.wait_group %0;" :: "n"(N) : "memory");
}
__device__ __forceinline__ float lds32(u32 a){
    float v; asm volatile("ld.shared.f32 %0, [%1];" : "=f"(v) : "r"(a));
    return v;
}
__device__ __forceinline__ u32 lds32u(u32 a){
    u32 v; asm volatile("ld.shared.b32 %0, [%1];" : "=r"(v) : "r"(a));
    return v;
}
__device__ __forceinline__ void mma8(float (&d)[4], const u32 (&a)[4], u32 b0, u32 b1){
    asm volatile("mma.sync.aligned.m16n8k8.row.col.f32.tf32.tf32.f32 "
        "{%0,%1,%2,%3}, {%4,%5,%6,%7}, {%8,%9}, {%0,%1,%2,%3};"
        : "+f"(d[0]), "+f"(d[1]), "+f"(d[2]), "+f"(d[3])
        : "r"(a[0]), "r"(a[1]), "r"(a[2]), "r"(a[3]), "r"(b0), "r"(b1));
}

// ---------------- W pre-split ----------------
__global__ __launch_bounds__(256) void conv_w_kernel(const float* __restrict__ W){
    const int gid = blockIdx.x * 256 + threadIdx.x;
    #pragma unroll
    for (int i = 0; i < 4; i++) {
        const int idx = gid + i * 65536;
        u32 hi, lo;
        split_tf32(W[idx], hi, lo);
        g_Whi[idx] = hi;
        g_Wlo[idx] = lo;
    }
}

// ---------------- GEMM (split-K, 3xTF32) ----------------
__global__ __launch_bounds__(256, 1) void gemm_kernel(
    const float* __restrict__ x, int M)
{
    extern __shared__ char smem[];
    const u32 sbase = smem_u32(smem);
    const int tid  = threadIdx.x;
    const int wid  = tid >> 5;
    const int lane = tid & 31;
    const int m_base = blockIdx.x * BM;
    const int split  = blockIdx.y;
    const int k0     = split * KSPLIT;

    // cp.async source/dst mapping (identical to R6)
    const float* srcA[4]; u32 dstA[4];
    #pragma unroll
    for (int i = 0; i < 4; i++) {
        const int idx = tid + 256 * i;
        const int row = idx >> 3, f4 = idx & 7;
        srcA[i] = x + (size_t)(m_base + row) * K_DIM + k0 + f4 * 4;
        dstA[i] = row * (ROWSTR * 4) + f4 * 16;
    }
    const u32* srcBH[2]; const u32* srcBL[2]; u32 dstB[2];
    #pragma unroll
    for (int i = 0; i < 2; i++) {
        const int idx = tid + 256 * i;
        const int row = idx >> 3, f4 = idx & 7;
        srcBH[i] = g_Whi + (size_t)row * K_DIM + k0 + f4 * 4;
        srcBL[i] = g_Wlo + (size_t)row * K_DIM + k0 + f4 * 4;
        dstB[i] = row * (ROWSTR * 4) + f4 * 16;
    }

    #define ISSUE_STAGE(ch) do {                                            \
        const u32 st = sbase + ((ch) & (NSTAGE - 1)) * STAGE_BYTES;         \
        const int ko = (ch) * BK;                                           \
        _Pragma("unroll")                                                   \
        for (int i = 0; i < 4; i++) cpa16(st + dstA[i], srcA[i] + ko);      \
        _Pragma("unroll")                                                   \
        for (int i = 0; i < 2; i++) cpa16(st + OFF_BH + dstB[i], srcBH[i] + ko); \
        _Pragma("unroll")                                                   \
        for (int i = 0; i < 2; i++) cpa16(st + OFF_BL + dstB[i], srcBL[i] + ko); \
    } while (0)

    ISSUE_STAGE(0); cpa_commit();
    ISSUE_STAGE(1); cpa_commit();
    ISSUE_STAGE(2); cpa_commit();

    // Warp tile: m32 x n32.  4 m-bands x 2 n-halves.
    float c[2][4][4];
    #pragma unroll
    for (int mf = 0; mf < 2; mf++)
        #pragma unroll
        for (int nf = 0; nf < 4; nf++)
            #pragma unroll
            for (int q = 0; q < 4; q++) c[mf][nf][q] = 0.f;

    const int mRow = (wid & 3) * 32;            // m-band base
    const int nf0  = (wid >> 2) * 4;            // n-half: experts nf0*8 .. nf0*8+31
    const u32 aRow0 = (u32)(mRow + (lane >> 2)) * (ROWSTR * 4);
    const u32 aColOff = (u32)(lane & 3) * 4;
    const u32 bNOff = (u32)(nf0 * 8 + (lane >> 2)) * (ROWSTR * 4);
    const u32 bKOff = (u32)(lane & 3) * 4;

    #pragma unroll 1
    for (int ch = 0; ch < NCH; ch++) {
        cpa_wait<2>();
        __syncthreads();

        const u32 st = sbase + (ch & (NSTAGE - 1)) * STAGE_BYTES;
        #pragma unroll
        for (int ks = 0; ks < 4; ks++) {
            const u32 kb = (u32)ks * 32;  // 8 floats = 32 bytes
            u32 ahi[2][4], alo[2][4];
            #pragma unroll
            for (int mf = 0; mf < 2; mf++) {
                const u32 aA = st + aRow0 + (u32)mf * (16 * ROWSTR * 4) + kb + aColOff;
                float a0 = lds32(aA);
                float a1 = lds32(aA + 8 * ROWSTR * 4);
                float a2 = lds32(aA + 16);
                float a3 = lds32(aA + 8 * ROWSTR * 4 + 16);
                split_tf32(a0, ahi[mf][0], alo[mf][0]);
                split_tf32(a1, ahi[mf][1], alo[mf][1]);
                split_tf32(a2, ahi[mf][2], alo[mf][2]);
                split_tf32(a3, ahi[mf][3], alo[mf][3]);
            }

            #pragma unroll
            for (int nf = 0; nf < 4; nf++) {
                const u32 bA = st + (u32)nf * (8 * ROWSTR * 4) + bNOff + kb + bKOff;
                const u32 bh0 = lds32u(bA + OFF_BH);
                const u32 bh1 = lds32u(bA + OFF_BH + 16);
                const u32 bl0 = lds32u(bA + OFF_BL);
                const u32 bl1 = lds32u(bA + OFF_BL + 16);
                #pragma unroll
                for (int mf = 0; mf < 2; mf++) {
                    mma8(c[mf][nf], ahi[mf], bh0, bh1);   // hi*hi
                    mma8(c[mf][nf], ahi[mf], bl0, bl1);   // hi*lo
                    mma8(c[mf][nf], alo[mf], bh0, bh1);   // lo*hi
                }
            }
        }

        __syncthreads();
        const int cn = ch + 3;
        if (cn < NCH) ISSUE_STAGE(cn);
        cpa_commit();
    }

    // write partial logits [split][token][expert]
    const int col = (lane & 3) * 2;
    #pragma unroll
    for (int mf = 0; mf < 2; mf++) {
        const int t0 = m_base + mRow + mf * 16 + (lane >> 2);
        #pragma unroll
        for (int nf = 0; nf < 4; nf++) {
            float* p0 = g_partials + ((size_t)split * M + t0) * NE + (nf0 + nf) * 8 + col;
            *(float2*)p0            = make_float2(c[mf][nf][0], c[mf][nf][1]);
            *(float2*)(p0 + 8 * NE) = make_float2(c[mf][nf][2], c[mf][nf][3]);
        }
    }
    #undef ISSUE_STAGE
}

// ---------------- reduce + softmax + top2 ----------------
__global__ __launch_bounds__(256) void reduce_topk_kernel(
    float* __restrict__ out, int M, int write_idx)
{
    const int warp = threadIdx.x >> 5;
    const int lane = threadIdx.x & 31;
    const int t = blockIdx.x * 8 + warp;
    if (t >= M) return;

    float2 s = make_float2(0.f, 0.f);
    const float* p = g_partials + (size_t)t * NE + 2 * lane;
    #pragma unroll
    for (int si = 0; si < NSPLIT; si++) {
        float2 v = *(const float2*)(p + (size_t)si * M * NE);
        s.x += v.x; s.y += v.y;
    }

    float a1, a2; int i1, i2;
    if (s.x >= s.y) { a1 = s.x; i1 = 2 * lane;     a2 = s.y; i2 = 2 * lane + 1; }
    else            { a1 = s.y; i1 = 2 * lane + 1; a2 = s.x; i2 = 2 * lane;     }

    #pragma unroll
    for (int off = 16; off > 0; off >>= 1) {
        float b1 = __shfl_xor_sync(0xffffffffu, a1, off);
        float b2 = __shfl_xor_sync(0xffffffffu, a2, off);
        int  bi1 = __shfl_xor_sync(0xffffffffu, i1, off);
        int  bi2 = __shfl_xor_sync(0xffffffffu, i2, off);
        if (b1 > a1 || (b1 == a1 && bi1 < i1)) {
            if (b2 > a1 || (b2 == a1 && bi2 < i1)) { a1 = b1; i1 = bi1; a2 = b2; i2 = bi2; }
            else                                   { a2 = a1; i2 = i1;  a1 = b1; i1 = bi1; }
        } else {
            if (b1 > a2 || (b1 == a2 && bi1 < i2)) { a2 = b1; i2 = bi1; }
        }
    }

    float ex = __expf(s.x - a1) + __expf(s.y - a1);
    #pragma unroll
    for (int off = 16; off > 0; off >>= 1)
        ex += __shfl_xor_sync(0xffffffffu, ex, off);

    if (lane == 0) {
        const float inv = 1.0f / ex;
        out[2 * t + 0] = inv;
        out[2 * t + 1] = __expf(a2 - a1) * inv;
        if (write_idx) {
            out[2 * M + 2 * t + 0] = (float)i1;
            out[2 * M + 2 * t + 1] = (float)i2;
        }
    }
}

extern "C" void kernel_launch(void* const* d_in, const int* in_sizes, int n_in,
                              void* d_out, int out_size) {
    const float* x = (const float*)d_in[0];   // 8192 x 4096 fp32
    const float* W = (const float*)d_in[1];   // 64 x 4096 fp32
    float* out = (float*)d_out;

    const int M = in_sizes[0] / K_DIM;        // 8192
    const int write_idx = (out_size >= 4 * M) ? 1 : 0;

    cudaFuncSetAttribute(gemm_kernel,
                         cudaFuncAttributeMaxDynamicSharedMemorySize, SMEM_TOTAL);

    conv_w_kernel<<<256, 256>>>(W);
    dim3 grid(M / BM, NSPLIT);
    gemm_kernel<<<grid, 256, SMEM_TOTAL>>>(x, M);
    reduce_topk_kernel<<<(M + 7) / 8, 256>>>(out, M, write_idx);
}